// round 14
// baseline (speedup 1.0000x reference)
#include <cuda_runtime.h>
#include <math.h>

#define NN 4096
#define EE 131072
#define CC 64
#define SHD 16

// ---------------- scratch (static device globals; no runtime alloc) ----------
__device__ float g_hs[NN*CC];          // embedding output (layer-0 feat[:,:,0])
__device__ float g_feat[NN*SHD*CC];    // node features, X-MAJOR: [n][x][c]
__device__ float g_pos[NN*3];          // current positions
__device__ float g_len0[EE];           // initial edge lengths
__device__ float g_Y[EE*SHD];          // spherical harmonics per edge
__device__ float g_A[EE*CC];           // R * feat0 / 32
__device__ float g_T[EE*CC];           // x=0 total contribution / 32
__device__ int   g_cnt[NN];
__device__ int   g_off[NN+1];
__device__ int   g_cur[NN];
__device__ int   g_perm[EE];

// ---------------- init: zero hist, copy pos, zero out ------------------------
__global__ void k_init(const float* __restrict__ pos, float* __restrict__ out){
    int i = blockIdx.x*blockDim.x + threadIdx.x;
    if (i < NN) g_cnt[i] = 0;
    if (i < NN*3){ g_pos[i] = pos[i]; out[i] = 0.f; }
}

// ---------------- embedding: hs = [onehot(attr), temb] @ W + b ---------------
__global__ void k_embed(const int* __restrict__ attrs, const float* __restrict__ temb,
                        const float* __restrict__ W, const float* __restrict__ b){
    int i = blockIdx.x*blockDim.x + threadIdx.x;   // n*64 + c
    int n = i >> 6, c = i & 63;
    int a = attrs[n] - 1;
    float acc = b[c] + W[a*CC + c];
    #pragma unroll
    for (int t = 0; t < 32; t++) acc += temb[n*32 + t] * W[(5+t)*CC + c];
    g_hs[i] = acc;
}

// ---------------- counting sort of edges by recv -----------------------------
__global__ void k_hist(const int* __restrict__ ei){
    int e = blockIdx.x*blockDim.x + threadIdx.x;
    if (e < EE) atomicAdd(&g_cnt[ei[EE + e]], 1);
}

__global__ void k_scan(){
    __shared__ int sh[1024];
    int t = threadIdx.x;
    int4 v = *(const int4*)&g_cnt[t*4];
    int s1 = v.x, s2 = s1 + v.y, s3 = s2 + v.z, s4 = s3 + v.w;
    int val = s4;
    sh[t] = val;
    __syncthreads();
    for (int off = 1; off < 1024; off <<= 1){
        int add = (t >= off) ? sh[t - off] : 0;
        __syncthreads();
        val += add;
        sh[t] = val;
        __syncthreads();
    }
    int base = val - s4;
    int o0 = base, o1 = base + s1, o2 = base + s2, o3 = base + s3;
    g_off[t*4+0] = o0; g_off[t*4+1] = o1; g_off[t*4+2] = o2; g_off[t*4+3] = o3;
    g_cur[t*4+0] = o0; g_cur[t*4+1] = o1; g_cur[t*4+2] = o2; g_cur[t*4+3] = o3;
    if (t == 1023) g_off[NN] = val;
}

__global__ void k_scatter(const int* __restrict__ ei){
    int e = blockIdx.x*blockDim.x + threadIdx.x;
    if (e < EE){
        int r = ei[EE + e];
        int p = atomicAdd(&g_cur[r], 1);
        g_perm[p] = e;
    }
}

// ---------------- fused edge kernel -----------------------------------------
// 64 edges per block, 256 threads.
__global__ void k_edge(const int* __restrict__ ei,
                       const float* __restrict__ W1, const float* __restrict__ b1,
                       const float* __restrict__ W2, int layer){
    __shared__ float shH[64][65];
    __shared__ float shW[64][64];
    __shared__ float shY[64][16];
    __shared__ float shLen[64], shLen0[64];
    __shared__ int   shS[64];

    int e0 = blockIdx.x*64;
    int t  = threadIdx.x;   // 256

    // -- phase 0: W2 tile load + per-edge geometry --
    const float* W2l = W2 + layer*4096;
    for (int i = t; i < 4096; i += 256)
        shW[i>>6][i&63] = W2l[i];

    if (t < 64){
        int e = e0 + t;
        int s = ei[e], r = ei[EE + e];
        shS[t] = s;
        float vx = g_pos[r*3+0] - g_pos[s*3+0];
        float vy = g_pos[r*3+1] - g_pos[s*3+1];
        float vz = g_pos[r*3+2] - g_pos[s*3+2];
        float len = sqrtf(vx*vx + vy*vy + vz*vz);
        float len0;
        if (layer == 0){ len0 = len; g_len0[e] = len; }
        else           { len0 = g_len0[e]; }
        shLen[t] = len; shLen0[t] = len0;
        float il = 1.f / (len + 1e-9f);
        float x = vx*il, y = vy*il, z = vz*il;

        const float s3  = 1.7320508075688772f;
        const float c2  = 3.872983346207417f;
        const float c20 = 1.118033988749895f;
        const float c22 = 1.9364916731037085f;
        const float c3a = 2.0916500663351889f;
        const float c3b = 10.246950765959598f;
        const float c3c = 1.6201851746019651f;
        const float c30 = 1.3228756555322954f;
        const float c32 = 5.123475382979799f;
        float z2 = z*z, x2 = x*x, y2 = y*y;
        float4 y0 = make_float4(1.f, s3*x, s3*y, s3*z);
        float4 y1 = make_float4(c2*x*y, c2*y*z, c20*(3.f*z2 - 1.f), c2*x*z);
        float4 y2v= make_float4(c22*(x2 - y2), c3a*y*(3.f*x2 - y2), c3b*x*y*z, c3c*y*(5.f*z2 - 1.f));
        float4 y3 = make_float4(c30*z*(5.f*z2 - 3.f), c3c*x*(5.f*z2 - 1.f), c32*z*(x2 - y2), c3a*x*(x2 - 3.f*y2));
        float4* Ys = (float4*)&shY[t][0];
        Ys[0] = y0; Ys[1] = y1; Ys[2] = y2v; Ys[3] = y3;
        float4* Yg = (float4*)&g_Y[e*16];
        Yg[0] = y0; Yg[1] = y1; Yg[2] = y2v; Yg[3] = y3;
    }
    __syncthreads();

    // -- phase 1: radial hidden, silu. 4 threads per edge, 16 units each --
    {
        int el = t >> 2;            // edge 0..63
        int g  = t & 3;             // group 0..3
        float len  = shLen[el];
        float len0 = shLen0[el];
        const float* W1l = W1 + layer*128;   // [2][64]
        const float* b1l = b1 + layer*64;
        #pragma unroll
        for (int j = 0; j < 16; j++){
            int h = g*16 + j;
            float p = len0*W1l[h] + len*W1l[64 + h] + b1l[h];
            shH[el][h] = p / (1.f + __expf(-p));
        }
    }
    __syncthreads();

    // -- phase 2: GEMM + epilogue --
    int ty = t >> 4, tx = t & 15;      // ty: 4-edge group, tx: 4-channel group
    float acc[4][4] = {};
    #pragma unroll
    for (int k = 0; k < 64; k++){
        float4 b = *(const float4*)&shW[k][tx*4];
        #pragma unroll
        for (int i = 0; i < 4; i++){
            float a = shH[ty*4 + i][k];
            acc[i][0] += a*b.x; acc[i][1] += a*b.y; acc[i][2] += a*b.z; acc[i][3] += a*b.w;
        }
    }
    int col = tx*4;
    const float inv = 0.03125f;  // 1/32 (AVG)
    #pragma unroll
    for (int i = 0; i < 4; i++){
        int el = ty*4 + i;
        int e  = e0 + el;
        int s  = shS[el];
        float4 A4, T4;
        if (layer == 0){
            float4 h = *(const float4*)&g_hs[s*64 + col];
            A4.x = acc[i][0]*h.x*inv; A4.y = acc[i][1]*h.y*inv;
            A4.z = acc[i][2]*h.z*inv; A4.w = acc[i][3]*h.w*inv;
            T4.x = 2.f*A4.x; T4.y = 2.f*A4.y; T4.z = 2.f*A4.z; T4.w = 2.f*A4.w;
        } else {
            // x-major feat: [n][x][c] -> lanes (tx) read contiguous 256B per x
            const float* fb = &g_feat[s*1024 + col];
            float D0 = 0.f, D1 = 0.f, D2 = 0.f, D3 = 0.f;
            float4 f00 = *(const float4*)fb;   // x = 0
            #pragma unroll
            for (int x = 0; x < 16; x++){
                float4 fx = *(const float4*)&fb[x*64];
                float yx = shY[el][x];
                D0 += fx.x*yx; D1 += fx.y*yx; D2 += fx.z*yx; D3 += fx.w*yx;
            }
            float R0 = acc[i][0], R1 = acc[i][1], R2 = acc[i][2], R3 = acc[i][3];
            A4.x = R0*f00.x*inv; A4.y = R1*f00.y*inv; A4.z = R2*f00.z*inv; A4.w = R3*f00.w*inv;
            T4.x = A4.x + R0*D0*inv; T4.y = A4.y + R1*D1*inv;
            T4.z = A4.z + R2*D2*inv; T4.w = A4.w + R3*D3*inv;
        }
        *(float4*)&g_A[e*64 + col] = A4;
        *(float4*)&g_T[e*64 + col] = T4;
    }
}

// ---------------- per-node: gather + mix + gate + prod + mbv + pos -----------
__global__ void k_node(const float* __restrict__ Wmix, const float* __restrict__ Wprod,
                       const float* __restrict__ Wvec, float* __restrict__ out, int layer){
    int n = blockIdx.x;
    int t = threadIdx.x;   // 64 threads = channel
    __shared__ int   shE[8];
    __shared__ float shY[8][16];
    __shared__ float shA[64][16];
    __shared__ float shM[64][16];
    __shared__ float shG[64];
    __shared__ float shR[192];

    float acc[16];
    #pragma unroll
    for (int i = 0; i < 16; i++) acc[i] = 0.f;
    int beg = g_off[n], end = g_off[n+1];
    for (int base = beg; base < end; base += 8){
        int m = min(8, end - base);
        if (t < m) shE[t] = g_perm[base + t];
        __syncthreads();
        for (int i = t; i < m*16; i += 64) shY[i>>4][i&15] = g_Y[shE[i>>4]*16 + (i&15)];
        __syncthreads();
        for (int k = 0; k < m; k++){
            int e = shE[k];
            float a  = g_A[e*64 + t];
            float tt = g_T[e*64 + t];
            acc[0] += tt;
            #pragma unroll
            for (int x = 1; x < 16; x++) acc[x] += a * shY[k][x];
        }
        __syncthreads();
    }
    #pragma unroll
    for (int x = 0; x < 16; x++) shA[t][x] = acc[x];
    __syncthreads();

    // mix: per-SH-block channel mixing
    const float* WM = Wmix + layer*16384;
    float mix[16];
    #pragma unroll
    for (int x = 0; x < 16; x++) mix[x] = 0.f;
    for (int c = 0; c < 64; c++){
        float w0 = WM[          c*64 + t];
        float w1 = WM[ 4096 +   c*64 + t];
        float w2 = WM[ 8192 +   c*64 + t];
        float w3 = WM[12288 +   c*64 + t];
        const float4* ap = (const float4*)&shA[c][0];
        float4 a0 = ap[0], a1 = ap[1], a2 = ap[2], a3 = ap[3];
        mix[0]  += a0.x*w0;
        mix[1]  += a0.y*w1; mix[2]  += a0.z*w1; mix[3]  += a0.w*w1;
        mix[4]  += a1.x*w2; mix[5]  += a1.y*w2; mix[6]  += a1.z*w2; mix[7] += a1.w*w2;
        mix[8]  += a2.x*w2;
        mix[9]  += a2.y*w3; mix[10] += a2.z*w3; mix[11] += a2.w*w3;
        mix[12] += a3.x*w3; mix[13] += a3.y*w3; mix[14] += a3.z*w3; mix[15] += a3.w*w3;
    }
    float sv = mix[0];
    float gate = sv + sv*sv + sv*sv*sv;
    #pragma unroll
    for (int x = 0; x < 16; x++) shM[t][x] = mix[x];
    shG[t] = gate;
    __syncthreads();

    // prod: feats = mix + (mix*gate) @ Wprod
    const float* WP = Wprod + layer*4096;
    float f[16];
    #pragma unroll
    for (int x = 0; x < 16; x++) f[x] = mix[x];
    for (int c = 0; c < 64; c++){
        float wg = shG[c] * WP[c*64 + t];
        const float4* mp = (const float4*)&shM[c][0];
        float4 m0 = mp[0], m1 = mp[1], m2 = mp[2], m3 = mp[3];
        f[0]  += m0.x*wg; f[1]  += m0.y*wg; f[2]  += m0.z*wg; f[3]  += m0.w*wg;
        f[4]  += m1.x*wg; f[5]  += m1.y*wg; f[6]  += m1.z*wg; f[7]  += m1.w*wg;
        f[8]  += m2.x*wg; f[9]  += m2.y*wg; f[10] += m2.z*wg; f[11] += m2.w*wg;
        f[12] += m3.x*wg; f[13] += m3.y*wg; f[14] += m3.z*wg; f[15] += m3.w*wg;
    }
    // write feats X-MAJOR: g_feat[n][x][c]; per x the warp stores contiguous 128B
    #pragma unroll
    for (int x = 0; x < 16; x++)
        g_feat[n*1024 + x*64 + t] = f[x];

    // mbv = feats[:,1:4] . Wvec ; update pos & accumulate output
    float wv = Wvec[layer*64 + t];
    shR[t] = f[1]*wv; shR[64 + t] = f[2]*wv; shR[128 + t] = f[3]*wv;
    __syncthreads();
    if (t < 3){
        float sum = 0.f;
        #pragma unroll
        for (int i = 0; i < 64; i++) sum += shR[t*64 + i];
        g_pos[n*3 + t] += sum;
        out[n*3 + t]   += sum;
    }
}

// ---------------- launch ------------------------------------------------------
// Order puts k_edge(l0) at launch #4 (where ncu's capture window has landed),
// while preserving dependencies: edge needs init+embed only; sort feeds node.
extern "C" void kernel_launch(void* const* d_in, const int* in_sizes, int n_in,
                              void* d_out, int out_size){
    (void)in_sizes; (void)n_in; (void)out_size;
    const float* positions = (const float*)d_in[0];
    const int*   attrs     = (const int*)  d_in[1];
    const float* temb      = (const float*)d_in[2];
    const int*   ei        = (const int*)  d_in[3];
    const float* embW      = (const float*)d_in[4];
    const float* embb      = (const float*)d_in[5];
    const float* W1        = (const float*)d_in[6];
    const float* b1        = (const float*)d_in[7];
    const float* W2        = (const float*)d_in[8];
    const float* Wmix      = (const float*)d_in[9];
    const float* Wprod     = (const float*)d_in[10];
    const float* Wvec      = (const float*)d_in[11];
    float* out = (float*)d_out;

    k_init   <<<(NN*3 + 255)/256, 256>>>(positions, out);       // 1
    k_embed  <<<(NN*CC)/256,      256>>>(attrs, temb, embW, embb); // 2
    k_hist   <<<EE/256,           256>>>(ei);                   // 3
    k_edge   <<<EE/64,            256>>>(ei, W1, b1, W2, 0);    // 4  <- profile target
    k_scan   <<<1,               1024>>>();                     // 5
    k_scatter<<<EE/256,           256>>>(ei);                   // 6
    k_node   <<<NN,                64>>>(Wmix, Wprod, Wvec, out, 0); // 7
    k_edge   <<<EE/64,            256>>>(ei, W1, b1, W2, 1);    // 8
    k_node   <<<NN,                64>>>(Wmix, Wprod, Wvec, out, 1); // 9
}

// round 17
// speedup vs baseline: 1.5572x; 1.5572x over previous
#include <cuda_runtime.h>
#include <math.h>

#define NN 4096
#define EE 131072
#define CC 64
#define SHD 16

// ---------------- scratch (static device globals; no runtime alloc) ----------
__device__ float g_hs[NN*CC];          // embedding output (layer-0 feat[:,:,0])
__device__ float g_feat[NN*SHD*CC];    // node features, X-MAJOR: [n][x][c]
__device__ float g_pos[NN*3];          // current positions
__device__ float g_len0[EE];           // initial edge lengths
__device__ float g_Y[EE*SHD];          // spherical harmonics per edge
__device__ float g_A[EE*CC];           // R * feat0 / 32
__device__ float g_T[EE*CC];           // x=0 total contribution / 32
__device__ int   g_cnt[NN];
__device__ int   g_off[NN+1];
__device__ int   g_cur[NN];
__device__ int   g_perm[EE];

// ---------------- init: zero hist, copy pos, zero out ------------------------
__global__ void k_init(const float* __restrict__ pos, float* __restrict__ out){
    int i = blockIdx.x*blockDim.x + threadIdx.x;
    if (i < NN) g_cnt[i] = 0;
    if (i < NN*3){ g_pos[i] = pos[i]; out[i] = 0.f; }
}

// ---------------- embedding: hs = [onehot(attr), temb] @ W + b ---------------
__global__ void k_embed(const int* __restrict__ attrs, const float* __restrict__ temb,
                        const float* __restrict__ W, const float* __restrict__ b){
    int i = blockIdx.x*blockDim.x + threadIdx.x;   // n*64 + c
    int n = i >> 6, c = i & 63;
    int a = attrs[n] - 1;
    float acc = b[c] + W[a*CC + c];
    #pragma unroll
    for (int t = 0; t < 32; t++) acc += temb[n*32 + t] * W[(5+t)*CC + c];
    g_hs[i] = acc;
}

// ---------------- counting sort of edges by recv -----------------------------
__global__ void k_hist(const int* __restrict__ ei){
    int e = blockIdx.x*blockDim.x + threadIdx.x;
    if (e < EE) atomicAdd(&g_cnt[ei[EE + e]], 1);
}

__global__ void k_scan(){
    __shared__ int sh[1024];
    int t = threadIdx.x;
    int4 v = *(const int4*)&g_cnt[t*4];
    int s1 = v.x, s2 = s1 + v.y, s3 = s2 + v.z, s4 = s3 + v.w;
    int val = s4;
    sh[t] = val;
    __syncthreads();
    for (int off = 1; off < 1024; off <<= 1){
        int add = (t >= off) ? sh[t - off] : 0;
        __syncthreads();
        val += add;
        sh[t] = val;
        __syncthreads();
    }
    int base = val - s4;
    int o0 = base, o1 = base + s1, o2 = base + s2, o3 = base + s3;
    g_off[t*4+0] = o0; g_off[t*4+1] = o1; g_off[t*4+2] = o2; g_off[t*4+3] = o3;
    g_cur[t*4+0] = o0; g_cur[t*4+1] = o1; g_cur[t*4+2] = o2; g_cur[t*4+3] = o3;
    if (t == 1023) g_off[NN] = val;
}

__global__ void k_scatter(const int* __restrict__ ei){
    int e = blockIdx.x*blockDim.x + threadIdx.x;
    if (e < EE){
        int r = ei[EE + e];
        int p = atomicAdd(&g_cur[r], 1);
        g_perm[p] = e;
    }
}

// ---------------- fused edge kernel -----------------------------------------
// 64 edges per block, 256 threads.
// shHT is TRANSPOSED [k][e] (pad 68 so float4 at [k][e*4] stays 16B-aligned):
// GEMM inner loop does 2x LDS.128 per k instead of 4x LDS.32 + 1x LDS.128.
__global__ void k_edge(const int* __restrict__ ei,
                       const float* __restrict__ W1, const float* __restrict__ b1,
                       const float* __restrict__ W2, int layer){
    __shared__ float shHT[64][68];
    __shared__ float shW[64][64];
    __shared__ float shY[64][16];
    __shared__ float shLen[64], shLen0[64];
    __shared__ int   shS[64];

    int e0 = blockIdx.x*64;
    int t  = threadIdx.x;   // 256

    // -- phase 0: W2 tile load + per-edge geometry --
    const float* W2l = W2 + layer*4096;
    for (int i = t; i < 4096; i += 256)
        shW[i>>6][i&63] = W2l[i];

    if (t < 64){
        int e = e0 + t;
        int s = ei[e], r = ei[EE + e];
        shS[t] = s;
        float vx = g_pos[r*3+0] - g_pos[s*3+0];
        float vy = g_pos[r*3+1] - g_pos[s*3+1];
        float vz = g_pos[r*3+2] - g_pos[s*3+2];
        float len = sqrtf(vx*vx + vy*vy + vz*vz);
        float len0;
        if (layer == 0){ len0 = len; g_len0[e] = len; }
        else           { len0 = g_len0[e]; }
        shLen[t] = len; shLen0[t] = len0;
        float il = 1.f / (len + 1e-9f);
        float x = vx*il, y = vy*il, z = vz*il;

        const float s3  = 1.7320508075688772f;
        const float c2  = 3.872983346207417f;
        const float c20 = 1.118033988749895f;
        const float c22 = 1.9364916731037085f;
        const float c3a = 2.0916500663351889f;
        const float c3b = 10.246950765959598f;
        const float c3c = 1.6201851746019651f;
        const float c30 = 1.3228756555322954f;
        const float c32 = 5.123475382979799f;
        float z2 = z*z, x2 = x*x, y2 = y*y;
        float4 y0 = make_float4(1.f, s3*x, s3*y, s3*z);
        float4 y1 = make_float4(c2*x*y, c2*y*z, c20*(3.f*z2 - 1.f), c2*x*z);
        float4 y2v= make_float4(c22*(x2 - y2), c3a*y*(3.f*x2 - y2), c3b*x*y*z, c3c*y*(5.f*z2 - 1.f));
        float4 y3 = make_float4(c30*z*(5.f*z2 - 3.f), c3c*x*(5.f*z2 - 1.f), c32*z*(x2 - y2), c3a*x*(x2 - 3.f*y2));
        float4* Ys = (float4*)&shY[t][0];
        Ys[0] = y0; Ys[1] = y1; Ys[2] = y2v; Ys[3] = y3;
        float4* Yg = (float4*)&g_Y[e*16];
        Yg[0] = y0; Yg[1] = y1; Yg[2] = y2v; Yg[3] = y3;
    }
    __syncthreads();

    // -- phase 1: radial hidden, silu -> TRANSPOSED store shHT[h][el].
    //    thread t: el = t&63 (edge), hg = t>>6 (16 hidden units).
    //    Stores at [h][el]: warp lanes span el -> distinct banks, conflict-free.
    {
        int el = t & 63;
        int hg = t >> 6;
        float len  = shLen[el];
        float len0 = shLen0[el];
        const float* W1l = W1 + layer*128;   // [2][64]
        const float* b1l = b1 + layer*64;
        #pragma unroll
        for (int j = 0; j < 16; j++){
            int h = hg*16 + j;
            float p = len0*W1l[h] + len*W1l[64 + h] + b1l[h];
            shHT[h][el] = __fdividef(p, 1.f + __expf(-p));
        }
    }
    __syncthreads();

    // -- phase 2: GEMM + epilogue --
    int ty = t >> 4, tx = t & 15;      // ty: 4-edge group, tx: 4-channel group
    float acc[4][4] = {};
    #pragma unroll
    for (int k = 0; k < 64; k++){
        float4 a4 = *(const float4*)&shHT[k][ty*4];  // H[e..e+3][k], broadcast
        float4 b4 = *(const float4*)&shW[k][tx*4];
        acc[0][0] += a4.x*b4.x; acc[0][1] += a4.x*b4.y; acc[0][2] += a4.x*b4.z; acc[0][3] += a4.x*b4.w;
        acc[1][0] += a4.y*b4.x; acc[1][1] += a4.y*b4.y; acc[1][2] += a4.y*b4.z; acc[1][3] += a4.y*b4.w;
        acc[2][0] += a4.z*b4.x; acc[2][1] += a4.z*b4.y; acc[2][2] += a4.z*b4.z; acc[2][3] += a4.z*b4.w;
        acc[3][0] += a4.w*b4.x; acc[3][1] += a4.w*b4.y; acc[3][2] += a4.w*b4.z; acc[3][3] += a4.w*b4.w;
    }
    int col = tx*4;
    const float inv = 0.03125f;  // 1/32 (AVG)
    #pragma unroll
    for (int i = 0; i < 4; i++){
        int el = ty*4 + i;
        int e  = e0 + el;
        int s  = shS[el];
        float4 A4, T4;
        if (layer == 0){
            float4 h = *(const float4*)&g_hs[s*64 + col];
            A4.x = acc[i][0]*h.x*inv; A4.y = acc[i][1]*h.y*inv;
            A4.z = acc[i][2]*h.z*inv; A4.w = acc[i][3]*h.w*inv;
            T4.x = 2.f*A4.x; T4.y = 2.f*A4.y; T4.z = 2.f*A4.z; T4.w = 2.f*A4.w;
        } else {
            // x-major feat: [n][x][c] -> lanes (tx) read contiguous 256B per x
            const float* fb = &g_feat[s*1024 + col];
            float D0 = 0.f, D1 = 0.f, D2 = 0.f, D3 = 0.f;
            float4 f00 = *(const float4*)fb;   // x = 0
            #pragma unroll
            for (int x = 0; x < 16; x++){
                float4 fx = *(const float4*)&fb[x*64];
                float yx = shY[el][x];
                D0 += fx.x*yx; D1 += fx.y*yx; D2 += fx.z*yx; D3 += fx.w*yx;
            }
            float R0 = acc[i][0], R1 = acc[i][1], R2 = acc[i][2], R3 = acc[i][3];
            A4.x = R0*f00.x*inv; A4.y = R1*f00.y*inv; A4.z = R2*f00.z*inv; A4.w = R3*f00.w*inv;
            T4.x = A4.x + R0*D0*inv; T4.y = A4.y + R1*D1*inv;
            T4.z = A4.z + R2*D2*inv; T4.w = A4.w + R3*D3*inv;
        }
        *(float4*)&g_A[e*64 + col] = A4;
        *(float4*)&g_T[e*64 + col] = T4;
    }
}

// ---------------- per-node: gather + mix + gate + prod + mbv + pos -----------
__global__ void k_node(const float* __restrict__ Wmix, const float* __restrict__ Wprod,
                       const float* __restrict__ Wvec, float* __restrict__ out, int layer){
    int n = blockIdx.x;
    int t = threadIdx.x;   // 64 threads = channel
    __shared__ int   shE[8];
    __shared__ float shY[8][16];
    __shared__ float shA[64][16];
    __shared__ float shM[64][16];
    __shared__ float shG[64];
    __shared__ float shR[192];

    float acc[16];
    #pragma unroll
    for (int i = 0; i < 16; i++) acc[i] = 0.f;
    int beg = g_off[n], end = g_off[n+1];
    for (int base = beg; base < end; base += 8){
        int m = min(8, end - base);
        if (t < m) shE[t] = g_perm[base + t];
        __syncthreads();
        for (int i = t; i < m*16; i += 64) shY[i>>4][i&15] = g_Y[shE[i>>4]*16 + (i&15)];
        __syncthreads();
        for (int k = 0; k < m; k++){
            int e = shE[k];
            float a  = g_A[e*64 + t];
            float tt = g_T[e*64 + t];
            acc[0] += tt;
            #pragma unroll
            for (int x = 1; x < 16; x++) acc[x] += a * shY[k][x];
        }
        __syncthreads();
    }
    #pragma unroll
    for (int x = 0; x < 16; x++) shA[t][x] = acc[x];
    __syncthreads();

    // mix: per-SH-block channel mixing
    const float* WM = Wmix + layer*16384;
    float mix[16];
    #pragma unroll
    for (int x = 0; x < 16; x++) mix[x] = 0.f;
    for (int c = 0; c < 64; c++){
        float w0 = WM[          c*64 + t];
        float w1 = WM[ 4096 +   c*64 + t];
        float w2 = WM[ 8192 +   c*64 + t];
        float w3 = WM[12288 +   c*64 + t];
        const float4* ap = (const float4*)&shA[c][0];
        float4 a0 = ap[0], a1 = ap[1], a2 = ap[2], a3 = ap[3];
        mix[0]  += a0.x*w0;
        mix[1]  += a0.y*w1; mix[2]  += a0.z*w1; mix[3]  += a0.w*w1;
        mix[4]  += a1.x*w2; mix[5]  += a1.y*w2; mix[6]  += a1.z*w2; mix[7] += a1.w*w2;
        mix[8]  += a2.x*w2;
        mix[9]  += a2.y*w3; mix[10] += a2.z*w3; mix[11] += a2.w*w3;
        mix[12] += a3.x*w3; mix[13] += a3.y*w3; mix[14] += a3.z*w3; mix[15] += a3.w*w3;
    }
    float sv = mix[0];
    float gate = sv + sv*sv + sv*sv*sv;
    #pragma unroll
    for (int x = 0; x < 16; x++) shM[t][x] = mix[x];
    shG[t] = gate;
    __syncthreads();

    // prod: feats = mix + (mix*gate) @ Wprod
    const float* WP = Wprod + layer*4096;
    float f[16];
    #pragma unroll
    for (int x = 0; x < 16; x++) f[x] = mix[x];
    for (int c = 0; c < 64; c++){
        float wg = shG[c] * WP[c*64 + t];
        const float4* mp = (const float4*)&shM[c][0];
        float4 m0 = mp[0], m1 = mp[1], m2 = mp[2], m3 = mp[3];
        f[0]  += m0.x*wg; f[1]  += m0.y*wg; f[2]  += m0.z*wg; f[3]  += m0.w*wg;
        f[4]  += m1.x*wg; f[5]  += m1.y*wg; f[6]  += m1.z*wg; f[7]  += m1.w*wg;
        f[8]  += m2.x*wg; f[9]  += m2.y*wg; f[10] += m2.z*wg; f[11] += m2.w*wg;
        f[12] += m3.x*wg; f[13] += m3.y*wg; f[14] += m3.z*wg; f[15] += m3.w*wg;
    }
    // write feats X-MAJOR: g_feat[n][x][c]; per x the warp stores contiguous 128B
    #pragma unroll
    for (int x = 0; x < 16; x++)
        g_feat[n*1024 + x*64 + t] = f[x];

    // mbv = feats[:,1:4] . Wvec ; update pos & accumulate output
    float wv = Wvec[layer*64 + t];
    shR[t] = f[1]*wv; shR[64 + t] = f[2]*wv; shR[128 + t] = f[3]*wv;
    __syncthreads();
    if (t < 3){
        float sum = 0.f;
        #pragma unroll
        for (int i = 0; i < 64; i++) sum += shR[t*64 + i];
        g_pos[n*3 + t] += sum;
        out[n*3 + t]   += sum;
    }
}

// ---------------- launch ------------------------------------------------------
// k_edge(l0) stays at launch #4 (the ncu capture slot).
extern "C" void kernel_launch(void* const* d_in, const int* in_sizes, int n_in,
                              void* d_out, int out_size){
    (void)in_sizes; (void)n_in; (void)out_size;
    const float* positions = (const float*)d_in[0];
    const int*   attrs     = (const int*)  d_in[1];
    const float* temb      = (const float*)d_in[2];
    const int*   ei        = (const int*)  d_in[3];
    const float* embW      = (const float*)d_in[4];
    const float* embb      = (const float*)d_in[5];
    const float* W1        = (const float*)d_in[6];
    const float* b1        = (const float*)d_in[7];
    const float* W2        = (const float*)d_in[8];
    const float* Wmix      = (const float*)d_in[9];
    const float* Wprod     = (const float*)d_in[10];
    const float* Wvec      = (const float*)d_in[11];
    float* out = (float*)d_out;

    k_init   <<<(NN*3 + 255)/256, 256>>>(positions, out);       // 1
    k_embed  <<<(NN*CC)/256,      256>>>(attrs, temb, embW, embb); // 2
    k_hist   <<<EE/256,           256>>>(ei);                   // 3
    k_edge   <<<EE/64,            256>>>(ei, W1, b1, W2, 0);    // 4  <- profile target
    k_scan   <<<1,               1024>>>();                     // 5
    k_scatter<<<EE/256,           256>>>(ei);                   // 6
    k_node   <<<NN,                64>>>(Wmix, Wprod, Wvec, out, 0); // 7
    k_edge   <<<EE/64,            256>>>(ei, W1, b1, W2, 1);    // 8
    k_node   <<<NN,                64>>>(Wmix, Wprod, Wvec, out, 1); // 9
}